// round 13
// baseline (speedup 1.0000x reference)
#include <cuda_runtime.h>
#include <cuda_bf16.h>
#include <math.h>

#define DIMQ 4096
#define NQ 12
#define NL 6
#define BATCHQ 8192
#define KDIM 1024
#define ODIM 16

#define BM 128
#define BN 128
#define BK 64
#define TILE_BYTES 16384
#define STAGE_BYTES (4 * TILE_BYTES)
#define NSTAGE 3
#define N_ITERS (KDIM / BK)
#define N_TILES ((DIMQ / BN) * (BATCHQ / BM))   // 2048
#define GEMM_CTAS 148

#define ELEMS 4
#define CIRC_GRID (BATCHQ / ELEMS)              // 2048

#define XSPLIT_BLOCKS ((BATCHQ * KDIM / 4) / 256)   // 8192
#define WSPLIT_BLOCKS ((DIMQ * KDIM / 4) / 256)     // 4096

typedef unsigned long long u64;
typedef unsigned int u32;

__device__ float g_amp[(size_t)BATCHQ * DIMQ];
__device__ __nv_bfloat16 g_xhi[(size_t)BATCHQ * KDIM];
__device__ __nv_bfloat16 g_xlo[(size_t)BATCHQ * KDIM];
__device__ __nv_bfloat16 g_whi[(size_t)DIMQ * KDIM];
__device__ __nv_bfloat16 g_wlo[(size_t)DIMQ * KDIM];

__device__ __forceinline__ float clip10(float v) { return fminf(fmaxf(v, -10.f), 10.f); }

// ---- packed f32x2 helpers ----
__device__ __forceinline__ u64 pk2(float x, float y) {
    u64 r;
    asm("mov.b64 %0, {%1, %2};" : "=l"(r) : "r"(__float_as_uint(x)), "r"(__float_as_uint(y)));
    return r;
}
__device__ __forceinline__ void upk2(u64 v, float& x, float& y) {
    unsigned lo, hi;
    asm("mov.b64 {%0, %1}, %2;" : "=r"(lo), "=r"(hi) : "l"(v));
    x = __uint_as_float(lo); y = __uint_as_float(hi);
}
__device__ __forceinline__ u64 fma2(u64 a, u64 b, u64 c) {
    u64 d;
    asm("fma.rn.f32x2 %0, %1, %2, %3;" : "=l"(d) : "l"(a), "l"(b), "l"(c));
    return d;
}
__device__ __forceinline__ u64 mul2(u64 a, u64 b) {
    u64 d;
    asm("mul.rn.f32x2 %0, %1, %2;" : "=l"(d) : "l"(a), "l"(b));
    return d;
}
__device__ __forceinline__ u64 sw2(u64 v) {
    unsigned lo, hi;
    asm("mov.b64 {%0, %1}, %2;" : "=r"(lo), "=r"(hi) : "l"(v));
    u64 r;
    asm("mov.b64 %0, {%1, %2};" : "=l"(r) : "r"(hi), "r"(lo));
    return r;
}

// ---- smem / async helpers ----
__device__ __forceinline__ u32 smem_u32(const void* p) {
    u32 a;
    asm("{ .reg .u64 t; cvta.to.shared.u64 t, %1; cvt.u32.u64 %0, t; }" : "=r"(a) : "l"(p));
    return a;
}
__device__ __forceinline__ u32 sw128(u32 off) { return off ^ ((off >> 3) & 0x70); }
__device__ __forceinline__ void cp16(u32 dst, const void* src) {
    asm volatile("cp.async.cg.shared.global [%0], [%1], 16;" :: "r"(dst), "l"(src) : "memory");
}
template <int N> __device__ __forceinline__ void cp_wait() {
    asm volatile("cp.async.wait_group %0;" :: "n"(N) : "memory");
}
__device__ __forceinline__ void ldm_x4(u32 addr, u32& r0, u32& r1, u32& r2, u32& r3) {
    asm volatile("ldmatrix.sync.aligned.m8n8.x4.shared.b16 {%0,%1,%2,%3}, [%4];"
                 : "=r"(r0), "=r"(r1), "=r"(r2), "=r"(r3) : "r"(addr));
}
__device__ __forceinline__ void mma16816(float* c, const u32* a, const u32* b) {
    asm volatile(
        "mma.sync.aligned.m16n8k16.row.col.f32.bf16.bf16.f32 "
        "{%0,%1,%2,%3}, {%4,%5,%6,%7}, {%8,%9}, {%0,%1,%2,%3};"
        : "+f"(c[0]), "+f"(c[1]), "+f"(c[2]), "+f"(c[3])
        : "r"(a[0]), "r"(a[1]), "r"(a[2]), "r"(a[3]), "r"(b[0]), "r"(b[1]));
}

// ---------------------------------------------------------------------------
// Merged split kernel
// ---------------------------------------------------------------------------
__global__ __launch_bounds__(256) void split_kernel(const float* __restrict__ x,
                                                    const float* __restrict__ w)
{
    int bid = blockIdx.x;
    bool isX = (bid < XSPLIT_BLOCKS);
    const float* src = isX ? x : w;
    size_t base = isX ? (size_t)bid : (size_t)(bid - XSPLIT_BLOCKS);
    size_t i = base * 256 + threadIdx.x;

    float4 v = ((const float4*)src)[i];
    if (isX) {
        v.x = clip10(v.x); v.y = clip10(v.y); v.z = clip10(v.z); v.w = clip10(v.w);
    }
    __nv_bfloat16 h0 = __float2bfloat16_rn(v.x), h1 = __float2bfloat16_rn(v.y);
    __nv_bfloat16 h2 = __float2bfloat16_rn(v.z), h3 = __float2bfloat16_rn(v.w);
    __nv_bfloat16 l0 = __float2bfloat16_rn(v.x - __bfloat162float(h0));
    __nv_bfloat16 l1 = __float2bfloat16_rn(v.y - __bfloat162float(h1));
    __nv_bfloat16 l2 = __float2bfloat16_rn(v.z - __bfloat162float(h2));
    __nv_bfloat16 l3 = __float2bfloat16_rn(v.w - __bfloat162float(h3));
    uint2 oh, ol;
    oh.x = (u32)__bfloat16_as_ushort(h0) | ((u32)__bfloat16_as_ushort(h1) << 16);
    oh.y = (u32)__bfloat16_as_ushort(h2) | ((u32)__bfloat16_as_ushort(h3) << 16);
    ol.x = (u32)__bfloat16_as_ushort(l0) | ((u32)__bfloat16_as_ushort(l1) << 16);
    ol.y = (u32)__bfloat16_as_ushort(l2) | ((u32)__bfloat16_as_ushort(l3) << 16);
    if (isX) {
        ((uint2*)g_xhi)[i] = oh;
        ((uint2*)g_xlo)[i] = ol;
    } else {
        ((uint2*)g_whi)[i] = oh;
        ((uint2*)g_wlo)[i] = ol;
    }
}

// ---------------------------------------------------------------------------
// HMMA bf16 split GEMM — persistent CTAs, grid-stride over tiles,
// 3-stage cp.async pipeline, 1 sync/iter
// ---------------------------------------------------------------------------
__device__ __forceinline__ void load_stage(u32 tile0, int buf, int kt,
                                           int rowBase, int colBase, int tid)
{
    u32 SB = tile0 + buf * STAGE_BYTES;
    const __nv_bfloat16* a_h = g_xhi + (size_t)rowBase * KDIM + kt;
    const __nv_bfloat16* a_l = g_xlo + (size_t)rowBase * KDIM + kt;
    const __nv_bfloat16* b_h = g_whi + (size_t)colBase * KDIM + kt;
    const __nv_bfloat16* b_l = g_wlo + (size_t)colBase * KDIM + kt;
#pragma unroll
    for (int i = 0; i < 4; i++) {
        int lin = i * 256 + tid;
        int row = lin >> 3, seg = lin & 7;
        u32 so = sw128((u32)(row * 128 + seg * 16));
        size_t go = (size_t)row * KDIM + seg * 8;
        cp16(SB + 0 * TILE_BYTES + so, a_h + go);
        cp16(SB + 1 * TILE_BYTES + so, a_l + go);
        cp16(SB + 2 * TILE_BYTES + so, b_h + go);
        cp16(SB + 3 * TILE_BYTES + so, b_l + go);
    }
    asm volatile("cp.async.commit_group;" ::: "memory");
}

__global__ __launch_bounds__(256, 1) void mma_kernel(const float* __restrict__ bias)
{
    extern __shared__ char dsm[];
    __shared__ float bsh[BN];

    int tid = threadIdx.x;
    int wid = tid >> 5;
    int lane = tid & 31;
    int wm = (wid >> 2) * 64;
    int wn = (wid & 3) * 32;

    u32 tile0 = (smem_u32(dsm) + 1023u) & ~1023u;

    u32 aRowOff = (u32)((lane & 15) * 128 + (lane >> 4) * 16);
    u32 bRowOff = (u32)(((lane >> 4) * 8 + (lane & 7)) * 128 + ((lane >> 3) & 1) * 16);

    for (int tile = blockIdx.x; tile < N_TILES; tile += gridDim.x) {
        int rowBase = (tile / (DIMQ / BN)) * BM;
        int colBase = (tile % (DIMQ / BN)) * BN;

        __syncthreads();   // protect bsh from previous tile's epilogue readers
        if (tid < BN) bsh[tid] = bias[colBase + tid];

        float acc[4][4][4];
#pragma unroll
        for (int mi = 0; mi < 4; mi++)
#pragma unroll
            for (int ni = 0; ni < 4; ni++)
#pragma unroll
                for (int r = 0; r < 4; r++) acc[mi][ni][r] = 0.f;

        load_stage(tile0, 0, 0, rowBase, colBase, tid);
        load_stage(tile0, 1, BK, rowBase, colBase, tid);

        int buf = 0;
        for (int it = 0; it < N_ITERS; it++) {
            if (it == N_ITERS - 1) cp_wait<0>(); else cp_wait<1>();
            __syncthreads();
            if (it + 2 < N_ITERS) {
                int nbuf = buf + 2; if (nbuf >= NSTAGE) nbuf -= NSTAGE;
                load_stage(tile0, nbuf, (it + 2) * BK, rowBase, colBase, tid);
            }
            u32 SA_h = tile0 + buf * STAGE_BYTES;
            u32 SA_l = SA_h + TILE_BYTES;
            u32 SB_h = SA_h + 2 * TILE_BYTES;
            u32 SB_l = SA_h + 3 * TILE_BYTES;

#pragma unroll
            for (int ks = 0; ks < 4; ks++) {
                u32 ah[4][4], al[4][4];
#pragma unroll
                for (int mi = 0; mi < 4; mi++) {
                    u32 off = (u32)((wm + mi * 16) * 128 + ks * 32) + aRowOff;
                    u32 sa = sw128(off);
                    ldm_x4(SA_h + sa, ah[mi][0], ah[mi][1], ah[mi][2], ah[mi][3]);
                    ldm_x4(SA_l + sa, al[mi][0], al[mi][1], al[mi][2], al[mi][3]);
                }
                u32 bh[2][4], bl[2][4];
#pragma unroll
                for (int nt = 0; nt < 2; nt++) {
                    u32 off = (u32)((wn + nt * 16) * 128 + ks * 32) + bRowOff;
                    u32 sb = sw128(off);
                    ldm_x4(SB_h + sb, bh[nt][0], bh[nt][1], bh[nt][2], bh[nt][3]);
                    ldm_x4(SB_l + sb, bl[nt][0], bl[nt][1], bl[nt][2], bl[nt][3]);
                }
#pragma unroll
                for (int mi = 0; mi < 4; mi++)
#pragma unroll
                    for (int ni = 0; ni < 4; ni++)
                        mma16816(acc[mi][ni], ah[mi], &bh[ni >> 1][(ni & 1) * 2]);
#pragma unroll
                for (int mi = 0; mi < 4; mi++)
#pragma unroll
                    for (int ni = 0; ni < 4; ni++)
                        mma16816(acc[mi][ni], ah[mi], &bl[ni >> 1][(ni & 1) * 2]);
#pragma unroll
                for (int mi = 0; mi < 4; mi++)
#pragma unroll
                    for (int ni = 0; ni < 4; ni++)
                        mma16816(acc[mi][ni], al[mi], &bh[ni >> 1][(ni & 1) * 2]);
            }
            if (++buf >= NSTAGE) buf = 0;
        }

        int r0 = lane >> 2;
        int c0 = (lane & 3) * 2;
#pragma unroll
        for (int mi = 0; mi < 4; mi++) {
            int mrow = rowBase + wm + mi * 16 + r0;
            float* row0 = g_amp + (size_t)mrow * DIMQ;
            float* row1 = row0 + (size_t)8 * DIMQ;
#pragma unroll
            for (int ni = 0; ni < 4; ni++) {
                int col = wn + ni * 8 + c0;
                float2 v0 = make_float2(acc[mi][ni][0] + bsh[col], acc[mi][ni][1] + bsh[col + 1]);
                float2 v1 = make_float2(acc[mi][ni][2] + bsh[col], acc[mi][ni][3] + bsh[col + 1]);
                *(float2*)(row0 + colBase + col) = v0;
                *(float2*)(row1 + colBase + col) = v1;
            }
        }
    }
}

// ---------------------------------------------------------------------------
// Circuit kernel — 4 batch elements per CTA (prologue amortized), static smem
// ---------------------------------------------------------------------------
template <int BIT>
__device__ __forceinline__ void apply_local(u64 r[16], const u64* __restrict__ g)
{
    u64 c00rr = g[0], c00ii = g[1], c01rr = g[2], c01ii = g[3];
    u64 c10rr = g[4], c10ii = g[5], c11rr = g[6], c11ii = g[7];
#pragma unroll
    for (int i = 0; i < 16; i++) {
        if ((i >> BIT) & 1) continue;
        int j = i | (1 << BIT);
        u64 a0 = r[i], a1 = r[j];
        u64 a0s = sw2(a0), a1s = sw2(a1);
        r[i] = fma2(c00rr, a0, fma2(c00ii, a0s, fma2(c01rr, a1, mul2(c01ii, a1s))));
        r[j] = fma2(c10rr, a0, fma2(c10ii, a0s, fma2(c11rr, a1, mul2(c11ii, a1s))));
    }
}

__device__ __forceinline__ int perm_fn(int k)
{
    int idx = k;
    idx ^= ((idx >> 0) & 1) << 11;
#pragma unroll
    for (int c = 10; c >= 0; c--) {
        int bc = 11 - c, bt = 10 - c;
        idx ^= ((idx >> bc) & 1) << bt;
    }
    return idx;
}

#define SMSZ 4352

__global__ __launch_bounds__(256, 3) void circuit_kernel(const float* __restrict__ q_params,
                                                         const float* __restrict__ W_out,
                                                         const float* __restrict__ b_out,
                                                         float* __restrict__ out)
{
    __shared__ u64 st[SMSZ];
    __shared__ u64 Ug2[NL * NQ * 8];
    __shared__ float red[8];
    __shared__ float sez[NQ];

    int t = threadIdx.x;

    // ---- prologue (once per CTA, reused for ELEMS batch elements) ----
    if (t < NL * NQ) {
        float tx = q_params[t * 3 + 0];
        float ty = q_params[t * 3 + 1];
        float tz = q_params[t * 3 + 2];
        float cx, sx, cy, sy, cz, sz;
        sincosf(0.5f * tx, &sx, &cx);
        sincosf(0.5f * ty, &sy, &cy);
        sincosf(0.5f * tz, &sz, &cz);
        float2 M00 = make_float2(cy * cx, sy * sx);
        float2 M01 = make_float2(-sy * cx, -cy * sx);
        float2 M10 = make_float2(sy * cx, -cy * sx);
        float2 M11 = make_float2(cy * cx, -sy * sx);
        float2 u00 = make_float2(cz * M00.x + sz * M00.y, cz * M00.y - sz * M00.x);
        float2 u01 = make_float2(cz * M01.x + sz * M01.y, cz * M01.y - sz * M01.x);
        float2 u10 = make_float2(cz * M10.x - sz * M10.y, cz * M10.y + sz * M10.x);
        float2 u11 = make_float2(cz * M11.x - sz * M11.y, cz * M11.y + sz * M11.x);
        u64* g = &Ug2[t * 8];
        g[0] = pk2(u00.x, u00.x); g[1] = pk2(-u00.y, u00.y);
        g[2] = pk2(u01.x, u01.x); g[3] = pk2(-u01.y, u01.y);
        g[4] = pk2(u10.x, u10.x); g[5] = pk2(-u10.y, u10.y);
        g[6] = pk2(u11.x, u11.x); g[7] = pk2(-u11.y, u11.y);
    }

    u32 psp[8];
#pragma unroll
    for (int i = 0; i < 8; i++) {
        int k0 = (t << 4) | (2 * i);
        int a0 = perm_fn(k0);     a0 += a0 >> 4;
        int a1 = perm_fn(k0 | 1); a1 += a1 >> 4;
        psp[i] = (u32)a0 | ((u32)a1 << 16);
    }

    for (int e = 0; e < ELEMS; e++) {
        int b = blockIdx.x * ELEMS + e;
        __syncthreads();            // protect st/sez/red from previous element
        if (t < NQ) sez[t] = 0.f;

        u64 r[16];
        float loc = 0.f;
        const float* arow = g_amp + (size_t)b * DIMQ;
#pragma unroll
        for (int ii = 0; ii < 4; ii++) {
            float4 v = ((const float4*)arow)[t * 4 + ii];
            r[ii * 4 + 0] = pk2(v.x, 0.f);
            r[ii * 4 + 1] = pk2(v.y, 0.f);
            r[ii * 4 + 2] = pk2(v.z, 0.f);
            r[ii * 4 + 3] = pk2(v.w, 0.f);
            loc += v.x * v.x + v.y * v.y + v.z * v.z + v.w * v.w;
        }
#pragma unroll
        for (int o = 16; o > 0; o >>= 1) loc += __shfl_xor_sync(0xffffffffu, loc, o);
        if ((t & 31) == 0) red[t >> 5] = loc;
        __syncthreads();
        float tot = 0.f;
#pragma unroll
        for (int i = 0; i < 8; i++) tot += red[i];
        float nrm = sqrtf(tot);
        if (nrm > 1e-8f) {
            float s = 1.f / nrm;
            u64 ss = pk2(s, s);
#pragma unroll
            for (int i = 0; i < 16; i++) r[i] = mul2(r[i], ss);
        } else {
#pragma unroll
            for (int i = 0; i < 16; i++)
                r[i] = (t == 0 && i == 0) ? pk2(1.f, 0.f) : 0ull;
        }

        for (int l = 0; l < NL; l++) {
            int base = l * NQ;
            apply_local<0>(r, &Ug2[(base + 11) * 8]);
            apply_local<1>(r, &Ug2[(base + 10) * 8]);
            apply_local<2>(r, &Ug2[(base + 9) * 8]);
            apply_local<3>(r, &Ug2[(base + 8) * 8]);
            __syncthreads();
#pragma unroll
            for (int i = 0; i < 16; i++) {
                int k = (t << 4) | i;
                st[k + (k >> 4)] = r[i];
            }
            __syncthreads();
#pragma unroll
            for (int i = 0; i < 16; i++) {
                int k = ((t >> 4) << 8) | (i << 4) | (t & 15);
                r[i] = st[k + (k >> 4)];
            }
            apply_local<0>(r, &Ug2[(base + 7) * 8]);
            apply_local<1>(r, &Ug2[(base + 6) * 8]);
            apply_local<2>(r, &Ug2[(base + 5) * 8]);
            apply_local<3>(r, &Ug2[(base + 4) * 8]);
            __syncthreads();
#pragma unroll
            for (int i = 0; i < 16; i++) {
                int k = ((t >> 4) << 8) | (i << 4) | (t & 15);
                st[k + (k >> 4)] = r[i];
            }
            __syncthreads();
#pragma unroll
            for (int i = 0; i < 16; i++) {
                int k = (i << 8) | t;
                r[i] = st[k + (k >> 4)];
            }
            apply_local<0>(r, &Ug2[(base + 3) * 8]);
            apply_local<1>(r, &Ug2[(base + 2) * 8]);
            apply_local<2>(r, &Ug2[(base + 1) * 8]);
            apply_local<3>(r, &Ug2[(base + 0) * 8]);
            __syncthreads();
#pragma unroll
            for (int i = 0; i < 16; i++) {
                int k = (i << 8) | t;
                st[k + (k >> 4)] = r[i];
            }
            __syncthreads();
#pragma unroll
            for (int i = 0; i < 16; i++) {
                int a = (psp[i >> 1] >> ((i & 1) * 16)) & 0xFFFF;
                r[i] = st[a];
            }
        }

        float p[16];
        float ptot = 0.f;
#pragma unroll
        for (int i = 0; i < 16; i++) {
            float x, y;
            upk2(r[i], x, y);
            p[i] = x * x + y * y;
            ptot += p[i];
        }
        float sb[4];
#pragma unroll
        for (int bp = 0; bp < 4; bp++) {
            float s = 0.f;
#pragma unroll
            for (int i = 0; i < 16; i++) s += ((i >> bp) & 1) ? -p[i] : p[i];
            sb[bp] = s;
        }
#pragma unroll
        for (int q = 0; q < NQ; q++) {
            int bp = 11 - q;
            float v = (bp < 4) ? sb[bp] : (((t >> (bp - 4)) & 1) ? -ptot : ptot);
#pragma unroll
            for (int o = 16; o > 0; o >>= 1) v += __shfl_xor_sync(0xffffffffu, v, o);
            if ((t & 31) == 0) atomicAdd(&sez[q], v);
        }
        __syncthreads();

        if (t < ODIM) {
            float acc = b_out[t];
#pragma unroll
            for (int i = 0; i < NQ; i++) acc += W_out[t * NQ + i] * sez[i];
            out[(size_t)b * ODIM + t] = acc;
        }
    }
}

// ---------------------------------------------------------------------------
extern "C" void kernel_launch(void* const* d_in, const int* in_sizes, int n_in,
                              void* d_out, int out_size)
{
    const float* x        = (const float*)d_in[0];
    const float* W_in     = (const float*)d_in[1];
    const float* b_in     = (const float*)d_in[2];
    const float* q_params = (const float*)d_in[3];
    const float* W_out    = (const float*)d_in[4];
    const float* b_out    = (const float*)d_in[5];
    float* out = (float*)d_out;

    cudaFuncSetAttribute(mma_kernel, cudaFuncAttributeMaxDynamicSharedMemorySize,
                         NSTAGE * STAGE_BYTES + 1024);

    split_kernel<<<XSPLIT_BLOCKS + WSPLIT_BLOCKS, 256>>>(x, W_in);

    mma_kernel<<<GEMM_CTAS, 256, NSTAGE * STAGE_BYTES + 1024>>>(b_in);

    circuit_kernel<<<CIRC_GRID, 256>>>(q_params, W_out, b_out, out);
}

// round 14
// speedup vs baseline: 1.0012x; 1.0012x over previous
#include <cuda_runtime.h>
#include <cuda_bf16.h>
#include <math.h>

#define DIMQ 4096
#define NQ 12
#define NL 6
#define BATCHQ 8192
#define KDIM 1024
#define ODIM 16

#define BM 128
#define BN 128
#define BK 64
#define TILE_BYTES 16384
#define STAGE_BYTES (4 * TILE_BYTES)
#define NSTAGE 3
#define N_ITERS (KDIM / BK)

#define ELEMS 4
#define CIRC_GRID (BATCHQ / ELEMS)              // 2048

#define XSPLIT_BLOCKS ((BATCHQ * KDIM / 4) / 256)   // 8192
#define WSPLIT_BLOCKS ((DIMQ * KDIM / 4) / 256)     // 4096

typedef unsigned long long u64;
typedef unsigned int u32;

__device__ float g_amp[(size_t)BATCHQ * DIMQ];
__device__ __nv_bfloat16 g_xhi[(size_t)BATCHQ * KDIM];
__device__ __nv_bfloat16 g_xlo[(size_t)BATCHQ * KDIM];
__device__ __nv_bfloat16 g_whi[(size_t)DIMQ * KDIM];
__device__ __nv_bfloat16 g_wlo[(size_t)DIMQ * KDIM];

__device__ __forceinline__ float clip10(float v) { return fminf(fmaxf(v, -10.f), 10.f); }

// ---- packed f32x2 helpers ----
__device__ __forceinline__ u64 pk2(float x, float y) {
    u64 r;
    asm("mov.b64 %0, {%1, %2};" : "=l"(r) : "r"(__float_as_uint(x)), "r"(__float_as_uint(y)));
    return r;
}
__device__ __forceinline__ void upk2(u64 v, float& x, float& y) {
    unsigned lo, hi;
    asm("mov.b64 {%0, %1}, %2;" : "=r"(lo), "=r"(hi) : "l"(v));
    x = __uint_as_float(lo); y = __uint_as_float(hi);
}
__device__ __forceinline__ u64 fma2(u64 a, u64 b, u64 c) {
    u64 d;
    asm("fma.rn.f32x2 %0, %1, %2, %3;" : "=l"(d) : "l"(a), "l"(b), "l"(c));
    return d;
}
__device__ __forceinline__ u64 mul2(u64 a, u64 b) {
    u64 d;
    asm("mul.rn.f32x2 %0, %1, %2;" : "=l"(d) : "l"(a), "l"(b));
    return d;
}
__device__ __forceinline__ u64 sw2(u64 v) {
    unsigned lo, hi;
    asm("mov.b64 {%0, %1}, %2;" : "=r"(lo), "=r"(hi) : "l"(v));
    u64 r;
    asm("mov.b64 %0, {%1, %2};" : "=l"(r) : "r"(hi), "r"(lo));
    return r;
}

// ---- smem / async helpers ----
__device__ __forceinline__ u32 smem_u32(const void* p) {
    u32 a;
    asm("{ .reg .u64 t; cvta.to.shared.u64 t, %1; cvt.u32.u64 %0, t; }" : "=r"(a) : "l"(p));
    return a;
}
__device__ __forceinline__ u32 sw128(u32 off) { return off ^ ((off >> 3) & 0x70); }
__device__ __forceinline__ void cp16(u32 dst, const void* src) {
    asm volatile("cp.async.cg.shared.global [%0], [%1], 16;" :: "r"(dst), "l"(src) : "memory");
}
template <int N> __device__ __forceinline__ void cp_wait() {
    asm volatile("cp.async.wait_group %0;" :: "n"(N) : "memory");
}
__device__ __forceinline__ void ldm_x4(u32 addr, u32& r0, u32& r1, u32& r2, u32& r3) {
    asm volatile("ldmatrix.sync.aligned.m8n8.x4.shared.b16 {%0,%1,%2,%3}, [%4];"
                 : "=r"(r0), "=r"(r1), "=r"(r2), "=r"(r3) : "r"(addr));
}
__device__ __forceinline__ void mma16816(float* c, const u32* a, const u32* b) {
    asm volatile(
        "mma.sync.aligned.m16n8k16.row.col.f32.bf16.bf16.f32 "
        "{%0,%1,%2,%3}, {%4,%5,%6,%7}, {%8,%9}, {%0,%1,%2,%3};"
        : "+f"(c[0]), "+f"(c[1]), "+f"(c[2]), "+f"(c[3])
        : "r"(a[0]), "r"(a[1]), "r"(a[2]), "r"(a[3]), "r"(b[0]), "r"(b[1]));
}

// ---------------------------------------------------------------------------
// Merged split kernel
// ---------------------------------------------------------------------------
__global__ __launch_bounds__(256) void split_kernel(const float* __restrict__ x,
                                                    const float* __restrict__ w)
{
    int bid = blockIdx.x;
    bool isX = (bid < XSPLIT_BLOCKS);
    const float* src = isX ? x : w;
    size_t base = isX ? (size_t)bid : (size_t)(bid - XSPLIT_BLOCKS);
    size_t i = base * 256 + threadIdx.x;

    float4 v = ((const float4*)src)[i];
    if (isX) {
        v.x = clip10(v.x); v.y = clip10(v.y); v.z = clip10(v.z); v.w = clip10(v.w);
    }
    __nv_bfloat16 h0 = __float2bfloat16_rn(v.x), h1 = __float2bfloat16_rn(v.y);
    __nv_bfloat16 h2 = __float2bfloat16_rn(v.z), h3 = __float2bfloat16_rn(v.w);
    __nv_bfloat16 l0 = __float2bfloat16_rn(v.x - __bfloat162float(h0));
    __nv_bfloat16 l1 = __float2bfloat16_rn(v.y - __bfloat162float(h1));
    __nv_bfloat16 l2 = __float2bfloat16_rn(v.z - __bfloat162float(h2));
    __nv_bfloat16 l3 = __float2bfloat16_rn(v.w - __bfloat162float(h3));
    uint2 oh, ol;
    oh.x = (u32)__bfloat16_as_ushort(h0) | ((u32)__bfloat16_as_ushort(h1) << 16);
    oh.y = (u32)__bfloat16_as_ushort(h2) | ((u32)__bfloat16_as_ushort(h3) << 16);
    ol.x = (u32)__bfloat16_as_ushort(l0) | ((u32)__bfloat16_as_ushort(l1) << 16);
    ol.y = (u32)__bfloat16_as_ushort(l2) | ((u32)__bfloat16_as_ushort(l3) << 16);
    if (isX) {
        ((uint2*)g_xhi)[i] = oh;
        ((uint2*)g_xlo)[i] = ol;
    } else {
        ((uint2*)g_whi)[i] = oh;
        ((uint2*)g_wlo)[i] = ol;
    }
}

// ---------------------------------------------------------------------------
// HMMA bf16 split GEMM — R12-exact: 3-stage cp.async pipeline, 1 sync/iter
// ---------------------------------------------------------------------------
__device__ __forceinline__ void load_stage(u32 tile0, int buf, int kt,
                                           int rowBase, int colBase, int tid)
{
    u32 SB = tile0 + buf * STAGE_BYTES;
    const __nv_bfloat16* a_h = g_xhi + (size_t)rowBase * KDIM + kt;
    const __nv_bfloat16* a_l = g_xlo + (size_t)rowBase * KDIM + kt;
    const __nv_bfloat16* b_h = g_whi + (size_t)colBase * KDIM + kt;
    const __nv_bfloat16* b_l = g_wlo + (size_t)colBase * KDIM + kt;
#pragma unroll
    for (int i = 0; i < 4; i++) {
        int lin = i * 256 + tid;
        int row = lin >> 3, seg = lin & 7;
        u32 so = sw128((u32)(row * 128 + seg * 16));
        size_t go = (size_t)row * KDIM + seg * 8;
        cp16(SB + 0 * TILE_BYTES + so, a_h + go);
        cp16(SB + 1 * TILE_BYTES + so, a_l + go);
        cp16(SB + 2 * TILE_BYTES + so, b_h + go);
        cp16(SB + 3 * TILE_BYTES + so, b_l + go);
    }
    asm volatile("cp.async.commit_group;" ::: "memory");
}

__global__ __launch_bounds__(256, 1) void mma_kernel(const float* __restrict__ bias)
{
    extern __shared__ char dsm[];
    __shared__ float bsh[BN];

    int tid = threadIdx.x;
    int wid = tid >> 5;
    int lane = tid & 31;
    int rowBase = blockIdx.y * BM;
    int colBase = blockIdx.x * BN;
    int wm = (wid >> 2) * 64;
    int wn = (wid & 3) * 32;

    u32 tile0 = (smem_u32(dsm) + 1023u) & ~1023u;

    if (tid < BN) bsh[tid] = bias[colBase + tid];

    u32 aRowOff = (u32)((lane & 15) * 128 + (lane >> 4) * 16);
    u32 bRowOff = (u32)(((lane >> 4) * 8 + (lane & 7)) * 128 + ((lane >> 3) & 1) * 16);

    float acc[4][4][4];
#pragma unroll
    for (int mi = 0; mi < 4; mi++)
#pragma unroll
        for (int ni = 0; ni < 4; ni++)
#pragma unroll
            for (int r = 0; r < 4; r++) acc[mi][ni][r] = 0.f;

    load_stage(tile0, 0, 0, rowBase, colBase, tid);
    load_stage(tile0, 1, BK, rowBase, colBase, tid);

    int buf = 0;
    for (int it = 0; it < N_ITERS; it++) {
        if (it == N_ITERS - 1) cp_wait<0>(); else cp_wait<1>();
        __syncthreads();
        if (it + 2 < N_ITERS) {
            int nbuf = buf + 2; if (nbuf >= NSTAGE) nbuf -= NSTAGE;
            load_stage(tile0, nbuf, (it + 2) * BK, rowBase, colBase, tid);
        }
        u32 SA_h = tile0 + buf * STAGE_BYTES;
        u32 SA_l = SA_h + TILE_BYTES;
        u32 SB_h = SA_h + 2 * TILE_BYTES;
        u32 SB_l = SA_h + 3 * TILE_BYTES;

#pragma unroll
        for (int ks = 0; ks < 4; ks++) {
            u32 ah[4][4], al[4][4];
#pragma unroll
            for (int mi = 0; mi < 4; mi++) {
                u32 off = (u32)((wm + mi * 16) * 128 + ks * 32) + aRowOff;
                u32 sa = sw128(off);
                ldm_x4(SA_h + sa, ah[mi][0], ah[mi][1], ah[mi][2], ah[mi][3]);
                ldm_x4(SA_l + sa, al[mi][0], al[mi][1], al[mi][2], al[mi][3]);
            }
            u32 bh[2][4], bl[2][4];
#pragma unroll
            for (int nt = 0; nt < 2; nt++) {
                u32 off = (u32)((wn + nt * 16) * 128 + ks * 32) + bRowOff;
                u32 sb = sw128(off);
                ldm_x4(SB_h + sb, bh[nt][0], bh[nt][1], bh[nt][2], bh[nt][3]);
                ldm_x4(SB_l + sb, bl[nt][0], bl[nt][1], bl[nt][2], bl[nt][3]);
            }
#pragma unroll
            for (int mi = 0; mi < 4; mi++)
#pragma unroll
                for (int ni = 0; ni < 4; ni++)
                    mma16816(acc[mi][ni], ah[mi], &bh[ni >> 1][(ni & 1) * 2]);
#pragma unroll
            for (int mi = 0; mi < 4; mi++)
#pragma unroll
                for (int ni = 0; ni < 4; ni++)
                    mma16816(acc[mi][ni], ah[mi], &bl[ni >> 1][(ni & 1) * 2]);
#pragma unroll
            for (int mi = 0; mi < 4; mi++)
#pragma unroll
                for (int ni = 0; ni < 4; ni++)
                    mma16816(acc[mi][ni], al[mi], &bh[ni >> 1][(ni & 1) * 2]);
        }
        if (++buf >= NSTAGE) buf = 0;
    }

    int r0 = lane >> 2;
    int c0 = (lane & 3) * 2;
#pragma unroll
    for (int mi = 0; mi < 4; mi++) {
        int mrow = rowBase + wm + mi * 16 + r0;
        float* row0 = g_amp + (size_t)mrow * DIMQ;
        float* row1 = row0 + (size_t)8 * DIMQ;
#pragma unroll
        for (int ni = 0; ni < 4; ni++) {
            int col = wn + ni * 8 + c0;
            float2 v0 = make_float2(acc[mi][ni][0] + bsh[col], acc[mi][ni][1] + bsh[col + 1]);
            float2 v1 = make_float2(acc[mi][ni][2] + bsh[col], acc[mi][ni][3] + bsh[col + 1]);
            *(float2*)(row0 + colBase + col) = v0;
            *(float2*)(row1 + colBase + col) = v1;
        }
    }
}

// ---------------------------------------------------------------------------
// Circuit kernel — minimal-barrier exchanges (3 CTA barriers/layer instead of 6)
//   Ex1 A->B is warp-local (both layouts: warp w owns keys [512w,512w+512))
//   Ex2/Ex3 stores write exactly the addresses the same thread just read
// ---------------------------------------------------------------------------
template <int BIT>
__device__ __forceinline__ void apply_local(u64 r[16], const u64* __restrict__ g)
{
    u64 c00rr = g[0], c00ii = g[1], c01rr = g[2], c01ii = g[3];
    u64 c10rr = g[4], c10ii = g[5], c11rr = g[6], c11ii = g[7];
#pragma unroll
    for (int i = 0; i < 16; i++) {
        if ((i >> BIT) & 1) continue;
        int j = i | (1 << BIT);
        u64 a0 = r[i], a1 = r[j];
        u64 a0s = sw2(a0), a1s = sw2(a1);
        r[i] = fma2(c00rr, a0, fma2(c00ii, a0s, fma2(c01rr, a1, mul2(c01ii, a1s))));
        r[j] = fma2(c10rr, a0, fma2(c10ii, a0s, fma2(c11rr, a1, mul2(c11ii, a1s))));
    }
}

__device__ __forceinline__ int perm_fn(int k)
{
    int idx = k;
    idx ^= ((idx >> 0) & 1) << 11;
#pragma unroll
    for (int c = 10; c >= 0; c--) {
        int bc = 11 - c, bt = 10 - c;
        idx ^= ((idx >> bc) & 1) << bt;
    }
    return idx;
}

#define SMSZ 4352

__global__ __launch_bounds__(256, 3) void circuit_kernel(const float* __restrict__ q_params,
                                                         const float* __restrict__ W_out,
                                                         const float* __restrict__ b_out,
                                                         float* __restrict__ out)
{
    __shared__ u64 st[SMSZ];
    __shared__ u64 Ug2[NL * NQ * 8];
    __shared__ float red[8];
    __shared__ float sez[NQ];

    int t = threadIdx.x;

    // ---- prologue (once per CTA, reused for ELEMS batch elements) ----
    if (t < NL * NQ) {
        float tx = q_params[t * 3 + 0];
        float ty = q_params[t * 3 + 1];
        float tz = q_params[t * 3 + 2];
        float cx, sx, cy, sy, cz, sz;
        sincosf(0.5f * tx, &sx, &cx);
        sincosf(0.5f * ty, &sy, &cy);
        sincosf(0.5f * tz, &sz, &cz);
        float2 M00 = make_float2(cy * cx, sy * sx);
        float2 M01 = make_float2(-sy * cx, -cy * sx);
        float2 M10 = make_float2(sy * cx, -cy * sx);
        float2 M11 = make_float2(cy * cx, -sy * sx);
        float2 u00 = make_float2(cz * M00.x + sz * M00.y, cz * M00.y - sz * M00.x);
        float2 u01 = make_float2(cz * M01.x + sz * M01.y, cz * M01.y - sz * M01.x);
        float2 u10 = make_float2(cz * M10.x - sz * M10.y, cz * M10.y + sz * M10.x);
        float2 u11 = make_float2(cz * M11.x - sz * M11.y, cz * M11.y + sz * M11.x);
        u64* g = &Ug2[t * 8];
        g[0] = pk2(u00.x, u00.x); g[1] = pk2(-u00.y, u00.y);
        g[2] = pk2(u01.x, u01.x); g[3] = pk2(-u01.y, u01.y);
        g[4] = pk2(u10.x, u10.x); g[5] = pk2(-u10.y, u10.y);
        g[6] = pk2(u11.x, u11.x); g[7] = pk2(-u11.y, u11.y);
    }

    u32 psp[8];
#pragma unroll
    for (int i = 0; i < 8; i++) {
        int k0 = (t << 4) | (2 * i);
        int a0 = perm_fn(k0);     a0 += a0 >> 4;
        int a1 = perm_fn(k0 | 1); a1 += a1 >> 4;
        psp[i] = (u32)a0 | ((u32)a1 << 16);
    }

    for (int e = 0; e < ELEMS; e++) {
        int b = blockIdx.x * ELEMS + e;
        __syncthreads();            // protect st/sez/red from previous element
        if (t < NQ) sez[t] = 0.f;

        u64 r[16];
        float loc = 0.f;
        const float* arow = g_amp + (size_t)b * DIMQ;
#pragma unroll
        for (int ii = 0; ii < 4; ii++) {
            float4 v = ((const float4*)arow)[t * 4 + ii];
            r[ii * 4 + 0] = pk2(v.x, 0.f);
            r[ii * 4 + 1] = pk2(v.y, 0.f);
            r[ii * 4 + 2] = pk2(v.z, 0.f);
            r[ii * 4 + 3] = pk2(v.w, 0.f);
            loc += v.x * v.x + v.y * v.y + v.z * v.z + v.w * v.w;
        }
#pragma unroll
        for (int o = 16; o > 0; o >>= 1) loc += __shfl_xor_sync(0xffffffffu, loc, o);
        if ((t & 31) == 0) red[t >> 5] = loc;
        __syncthreads();
        float tot = 0.f;
#pragma unroll
        for (int i = 0; i < 8; i++) tot += red[i];
        float nrm = sqrtf(tot);
        if (nrm > 1e-8f) {
            float s = 1.f / nrm;
            u64 ss = pk2(s, s);
#pragma unroll
            for (int i = 0; i < 16; i++) r[i] = mul2(r[i], ss);
        } else {
#pragma unroll
            for (int i = 0; i < 16; i++)
                r[i] = (t == 0 && i == 0) ? pk2(1.f, 0.f) : 0ull;
        }

        for (int l = 0; l < NL; l++) {
            int base = l * NQ;
            apply_local<0>(r, &Ug2[(base + 11) * 8]);
            apply_local<1>(r, &Ug2[(base + 10) * 8]);
            apply_local<2>(r, &Ug2[(base + 9) * 8]);
            apply_local<3>(r, &Ug2[(base + 8) * 8]);
            // Ex1 A->B: warp-local (both layouts keep keys within warp's 512-block)
            __syncthreads();   // vs previous cross-warp perm-gather reads
#pragma unroll
            for (int i = 0; i < 16; i++) {
                int k = (t << 4) | i;
                st[k + (k >> 4)] = r[i];
            }
            __syncwarp();
#pragma unroll
            for (int i = 0; i < 16; i++) {
                int k = ((t >> 4) << 8) | (i << 4) | (t & 15);
                r[i] = st[k + (k >> 4)];
            }
            apply_local<0>(r, &Ug2[(base + 7) * 8]);
            apply_local<1>(r, &Ug2[(base + 6) * 8]);
            apply_local<2>(r, &Ug2[(base + 5) * 8]);
            apply_local<3>(r, &Ug2[(base + 4) * 8]);
            // Ex2 B->C: store writes exactly the addresses this thread read in Ex1
            // (same formula, bijective) -> no pre-store sync needed
#pragma unroll
            for (int i = 0; i < 16; i++) {
                int k = ((t >> 4) << 8) | (i << 4) | (t & 15);
                st[k + (k >> 4)] = r[i];
            }
            __syncthreads();   // C-layout load is cross-warp
#pragma unroll
            for (int i = 0; i < 16; i++) {
                int k = (i << 8) | t;
                r[i] = st[k + (k >> 4)];
            }
            apply_local<0>(r, &Ug2[(base + 3) * 8]);
            apply_local<1>(r, &Ug2[(base + 2) * 8]);
            apply_local<2>(r, &Ug2[(base + 1) * 8]);
            apply_local<3>(r, &Ug2[(base + 0) * 8]);
            // Ex3: store writes exactly the addresses this thread read in Ex2
            // -> no pre-store sync needed
#pragma unroll
            for (int i = 0; i < 16; i++) {
                int k = (i << 8) | t;
                st[k + (k >> 4)] = r[i];
            }
            __syncthreads();   // perm gather is cross-warp
#pragma unroll
            for (int i = 0; i < 16; i++) {
                int a = (psp[i >> 1] >> ((i & 1) * 16)) & 0xFFFF;
                r[i] = st[a];
            }
        }

        float p[16];
        float ptot = 0.f;
#pragma unroll
        for (int i = 0; i < 16; i++) {
            float x, y;
            upk2(r[i], x, y);
            p[i] = x * x + y * y;
            ptot += p[i];
        }
        float sb[4];
#pragma unroll
        for (int bp = 0; bp < 4; bp++) {
            float s = 0.f;
#pragma unroll
            for (int i = 0; i < 16; i++) s += ((i >> bp) & 1) ? -p[i] : p[i];
            sb[bp] = s;
        }
#pragma unroll
        for (int q = 0; q < NQ; q++) {
            int bp = 11 - q;
            float v = (bp < 4) ? sb[bp] : (((t >> (bp - 4)) & 1) ? -ptot : ptot);
#pragma unroll
            for (int o = 16; o > 0; o >>= 1) v += __shfl_xor_sync(0xffffffffu, v, o);
            if ((t & 31) == 0) atomicAdd(&sez[q], v);
        }
        __syncthreads();

        if (t < ODIM) {
            float acc = b_out[t];
#pragma unroll
            for (int i = 0; i < NQ; i++) acc += W_out[t * NQ + i] * sez[i];
            out[(size_t)b * ODIM + t] = acc;
        }
    }
}

// ---------------------------------------------------------------------------
extern "C" void kernel_launch(void* const* d_in, const int* in_sizes, int n_in,
                              void* d_out, int out_size)
{
    const float* x        = (const float*)d_in[0];
    const float* W_in     = (const float*)d_in[1];
    const float* b_in     = (const float*)d_in[2];
    const float* q_params = (const float*)d_in[3];
    const float* W_out    = (const float*)d_in[4];
    const float* b_out    = (const float*)d_in[5];
    float* out = (float*)d_out;

    cudaFuncSetAttribute(mma_kernel, cudaFuncAttributeMaxDynamicSharedMemorySize,
                         NSTAGE * STAGE_BYTES + 1024);

    split_kernel<<<XSPLIT_BLOCKS + WSPLIT_BLOCKS, 256>>>(x, W_in);

    dim3 gmm(DIMQ / BN, BATCHQ / BM);
    mma_kernel<<<gmm, 256, NSTAGE * STAGE_BYTES + 1024>>>(b_in);

    circuit_kernel<<<CIRC_GRID, 256>>>(q_params, W_out, b_out, out);
}

// round 15
// speedup vs baseline: 1.0028x; 1.0016x over previous
#include <cuda_runtime.h>
#include <cuda_bf16.h>
#include <math.h>

#define DIMQ 4096
#define NQ 12
#define NL 6
#define BATCHQ 8192
#define KDIM 1024
#define ODIM 16

// GEMM: 128x64 tile, 2-stage, 2 CTAs/SM
#define BM 128
#define BN 64
#define BK 64
#define A_TILE 16384                 // 128 rows x 128 B
#define B_TILE 8192                  // 64 rows x 128 B
#define STAGE_BYTES (2 * A_TILE + 2 * B_TILE)   // 48 KB
#define N_ITERS (KDIM / BK)          // 16

#define ELEMS 4
#define CIRC_GRID (BATCHQ / ELEMS)              // 2048

#define XSPLIT_BLOCKS ((BATCHQ * KDIM / 4) / 256)   // 8192
#define WSPLIT_BLOCKS ((DIMQ * KDIM / 4) / 256)     // 4096

typedef unsigned long long u64;
typedef unsigned int u32;

__device__ float g_amp[(size_t)BATCHQ * DIMQ];
__device__ __nv_bfloat16 g_xhi[(size_t)BATCHQ * KDIM];
__device__ __nv_bfloat16 g_xlo[(size_t)BATCHQ * KDIM];
__device__ __nv_bfloat16 g_whi[(size_t)DIMQ * KDIM];
__device__ __nv_bfloat16 g_wlo[(size_t)DIMQ * KDIM];

__device__ __forceinline__ float clip10(float v) { return fminf(fmaxf(v, -10.f), 10.f); }

// ---- packed f32x2 helpers ----
__device__ __forceinline__ u64 pk2(float x, float y) {
    u64 r;
    asm("mov.b64 %0, {%1, %2};" : "=l"(r) : "r"(__float_as_uint(x)), "r"(__float_as_uint(y)));
    return r;
}
__device__ __forceinline__ void upk2(u64 v, float& x, float& y) {
    unsigned lo, hi;
    asm("mov.b64 {%0, %1}, %2;" : "=r"(lo), "=r"(hi) : "l"(v));
    x = __uint_as_float(lo); y = __uint_as_float(hi);
}
__device__ __forceinline__ u64 fma2(u64 a, u64 b, u64 c) {
    u64 d;
    asm("fma.rn.f32x2 %0, %1, %2, %3;" : "=l"(d) : "l"(a), "l"(b), "l"(c));
    return d;
}
__device__ __forceinline__ u64 mul2(u64 a, u64 b) {
    u64 d;
    asm("mul.rn.f32x2 %0, %1, %2;" : "=l"(d) : "l"(a), "l"(b));
    return d;
}
__device__ __forceinline__ u64 sw2(u64 v) {
    unsigned lo, hi;
    asm("mov.b64 {%0, %1}, %2;" : "=r"(lo), "=r"(hi) : "l"(v));
    u64 r;
    asm("mov.b64 %0, {%1, %2};" : "=l"(r) : "r"(hi), "r"(lo));
    return r;
}

// ---- smem / async helpers ----
__device__ __forceinline__ u32 smem_u32(const void* p) {
    u32 a;
    asm("{ .reg .u64 t; cvta.to.shared.u64 t, %1; cvt.u32.u64 %0, t; }" : "=r"(a) : "l"(p));
    return a;
}
__device__ __forceinline__ u32 sw128(u32 off) { return off ^ ((off >> 3) & 0x70); }
__device__ __forceinline__ void cp16(u32 dst, const void* src) {
    asm volatile("cp.async.cg.shared.global [%0], [%1], 16;" :: "r"(dst), "l"(src) : "memory");
}
template <int N> __device__ __forceinline__ void cp_wait() {
    asm volatile("cp.async.wait_group %0;" :: "n"(N) : "memory");
}
__device__ __forceinline__ void ldm_x4(u32 addr, u32& r0, u32& r1, u32& r2, u32& r3) {
    asm volatile("ldmatrix.sync.aligned.m8n8.x4.shared.b16 {%0,%1,%2,%3}, [%4];"
                 : "=r"(r0), "=r"(r1), "=r"(r2), "=r"(r3) : "r"(addr));
}
__device__ __forceinline__ void mma16816(float* c, const u32* a, const u32* b) {
    asm volatile(
        "mma.sync.aligned.m16n8k16.row.col.f32.bf16.bf16.f32 "
        "{%0,%1,%2,%3}, {%4,%5,%6,%7}, {%8,%9}, {%0,%1,%2,%3};"
        : "+f"(c[0]), "+f"(c[1]), "+f"(c[2]), "+f"(c[3])
        : "r"(a[0]), "r"(a[1]), "r"(a[2]), "r"(a[3]), "r"(b[0]), "r"(b[1]));
}

// ---------------------------------------------------------------------------
// Merged split kernel
// ---------------------------------------------------------------------------
__global__ __launch_bounds__(256) void split_kernel(const float* __restrict__ x,
                                                    const float* __restrict__ w)
{
    int bid = blockIdx.x;
    bool isX = (bid < XSPLIT_BLOCKS);
    const float* src = isX ? x : w;
    size_t base = isX ? (size_t)bid : (size_t)(bid - XSPLIT_BLOCKS);
    size_t i = base * 256 + threadIdx.x;

    float4 v = ((const float4*)src)[i];
    if (isX) {
        v.x = clip10(v.x); v.y = clip10(v.y); v.z = clip10(v.z); v.w = clip10(v.w);
    }
    __nv_bfloat16 h0 = __float2bfloat16_rn(v.x), h1 = __float2bfloat16_rn(v.y);
    __nv_bfloat16 h2 = __float2bfloat16_rn(v.z), h3 = __float2bfloat16_rn(v.w);
    __nv_bfloat16 l0 = __float2bfloat16_rn(v.x - __bfloat162float(h0));
    __nv_bfloat16 l1 = __float2bfloat16_rn(v.y - __bfloat162float(h1));
    __nv_bfloat16 l2 = __float2bfloat16_rn(v.z - __bfloat162float(h2));
    __nv_bfloat16 l3 = __float2bfloat16_rn(v.w - __bfloat162float(h3));
    uint2 oh, ol;
    oh.x = (u32)__bfloat16_as_ushort(h0) | ((u32)__bfloat16_as_ushort(h1) << 16);
    oh.y = (u32)__bfloat16_as_ushort(h2) | ((u32)__bfloat16_as_ushort(h3) << 16);
    ol.x = (u32)__bfloat16_as_ushort(l0) | ((u32)__bfloat16_as_ushort(l1) << 16);
    ol.y = (u32)__bfloat16_as_ushort(l2) | ((u32)__bfloat16_as_ushort(l3) << 16);
    if (isX) {
        ((uint2*)g_xhi)[i] = oh;
        ((uint2*)g_xlo)[i] = ol;
    } else {
        ((uint2*)g_whi)[i] = oh;
        ((uint2*)g_wlo)[i] = ol;
    }
}

// ---------------------------------------------------------------------------
// HMMA bf16 split GEMM — 128x64 tile, 2-stage double buffer, 2 CTAs/SM
// ---------------------------------------------------------------------------
__device__ __forceinline__ void load_stage(u32 tile0, int buf, int kt,
                                           int rowBase, int colBase, int tid)
{
    u32 SB = tile0 + buf * STAGE_BYTES;
    const __nv_bfloat16* a_h = g_xhi + (size_t)rowBase * KDIM + kt;
    const __nv_bfloat16* a_l = g_xlo + (size_t)rowBase * KDIM + kt;
    const __nv_bfloat16* b_h = g_whi + (size_t)colBase * KDIM + kt;
    const __nv_bfloat16* b_l = g_wlo + (size_t)colBase * KDIM + kt;
#pragma unroll
    for (int i = 0; i < 4; i++) {          // A: 128 rows x 8 segs = 1024
        int lin = i * 256 + tid;
        int row = lin >> 3, seg = lin & 7;
        u32 so = sw128((u32)(row * 128 + seg * 16));
        size_t go = (size_t)row * KDIM + seg * 8;
        cp16(SB + so, a_h + go);
        cp16(SB + A_TILE + so, a_l + go);
    }
#pragma unroll
    for (int i = 0; i < 2; i++) {          // B: 64 rows x 8 segs = 512
        int lin = i * 256 + tid;
        int row = lin >> 3, seg = lin & 7;
        u32 so = sw128((u32)(row * 128 + seg * 16));
        size_t go = (size_t)row * KDIM + seg * 8;
        cp16(SB + 2 * A_TILE + so, b_h + go);
        cp16(SB + 2 * A_TILE + B_TILE + so, b_l + go);
    }
    asm volatile("cp.async.commit_group;" ::: "memory");
}

__global__ __launch_bounds__(256, 2) void mma_kernel(const float* __restrict__ bias)
{
    extern __shared__ char dsm[];
    __shared__ float bsh[BN];

    int tid = threadIdx.x;
    int wid = tid >> 5;
    int lane = tid & 31;
    int rowBase = blockIdx.y * BM;
    int colBase = blockIdx.x * BN;
    int wm = (wid >> 2) * 64;      // 2 M-halves of 64 rows
    int wn = (wid & 3) * 16;       // 4 N-quarters of 16 cols

    u32 tile0 = (smem_u32(dsm) + 1023u) & ~1023u;

    if (tid < BN) bsh[tid] = bias[colBase + tid];

    u32 aRowOff = (u32)((lane & 15) * 128 + (lane >> 4) * 16);
    u32 bRowOff = (u32)(((lane >> 4) * 8 + (lane & 7)) * 128 + ((lane >> 3) & 1) * 16);

    float acc[4][2][4];
#pragma unroll
    for (int mi = 0; mi < 4; mi++)
#pragma unroll
        for (int ni = 0; ni < 2; ni++)
#pragma unroll
            for (int r = 0; r < 4; r++) acc[mi][ni][r] = 0.f;

    load_stage(tile0, 0, 0, rowBase, colBase, tid);
    load_stage(tile0, 1, BK, rowBase, colBase, tid);

    for (int it = 0; it < N_ITERS; it++) {
        int buf = it & 1;
        if (it == N_ITERS - 1) cp_wait<0>(); else cp_wait<1>();
        __syncthreads();
        u32 SA_h = tile0 + buf * STAGE_BYTES;
        u32 SA_l = SA_h + A_TILE;
        u32 SB_h = SA_h + 2 * A_TILE;
        u32 SB_l = SB_h + B_TILE;

#pragma unroll
        for (int ks = 0; ks < 4; ks++) {
            u32 ah[4][4], al[4][4];
#pragma unroll
            for (int mi = 0; mi < 4; mi++) {
                u32 off = (u32)((wm + mi * 16) * 128 + ks * 32) + aRowOff;
                u32 sa = sw128(off);
                ldm_x4(SA_h + sa, ah[mi][0], ah[mi][1], ah[mi][2], ah[mi][3]);
                ldm_x4(SA_l + sa, al[mi][0], al[mi][1], al[mi][2], al[mi][3]);
            }
            u32 bh[4], bl[4];
            {
                u32 off = (u32)(wn * 128 + ks * 32) + bRowOff;
                u32 sb = sw128(off);
                ldm_x4(SB_h + sb, bh[0], bh[1], bh[2], bh[3]);
                ldm_x4(SB_l + sb, bl[0], bl[1], bl[2], bl[3]);
            }
#pragma unroll
            for (int mi = 0; mi < 4; mi++)
#pragma unroll
                for (int ni = 0; ni < 2; ni++)
                    mma16816(acc[mi][ni], ah[mi], &bh[ni * 2]);
#pragma unroll
            for (int mi = 0; mi < 4; mi++)
#pragma unroll
                for (int ni = 0; ni < 2; ni++)
                    mma16816(acc[mi][ni], ah[mi], &bl[ni * 2]);
#pragma unroll
            for (int mi = 0; mi < 4; mi++)
#pragma unroll
                for (int ni = 0; ni < 2; ni++)
                    mma16816(acc[mi][ni], al[mi], &bh[ni * 2]);
        }
        __syncthreads();
        if (it + 2 < N_ITERS) load_stage(tile0, buf, (it + 2) * BK, rowBase, colBase, tid);
    }

    int r0 = lane >> 2;
    int c0 = (lane & 3) * 2;
#pragma unroll
    for (int mi = 0; mi < 4; mi++) {
        int mrow = rowBase + wm + mi * 16 + r0;
        float* row0 = g_amp + (size_t)mrow * DIMQ;
        float* row1 = row0 + (size_t)8 * DIMQ;
#pragma unroll
        for (int ni = 0; ni < 2; ni++) {
            int col = wn + ni * 8 + c0;
            float2 v0 = make_float2(acc[mi][ni][0] + bsh[col], acc[mi][ni][1] + bsh[col + 1]);
            float2 v1 = make_float2(acc[mi][ni][2] + bsh[col], acc[mi][ni][3] + bsh[col + 1]);
            *(float2*)(row0 + colBase + col) = v0;
            *(float2*)(row1 + colBase + col) = v1;
        }
    }
}

// ---------------------------------------------------------------------------
// Circuit kernel — R14 form (minimal barriers, ELEMS=4)
// ---------------------------------------------------------------------------
template <int BIT>
__device__ __forceinline__ void apply_local(u64 r[16], const u64* __restrict__ g)
{
    u64 c00rr = g[0], c00ii = g[1], c01rr = g[2], c01ii = g[3];
    u64 c10rr = g[4], c10ii = g[5], c11rr = g[6], c11ii = g[7];
#pragma unroll
    for (int i = 0; i < 16; i++) {
        if ((i >> BIT) & 1) continue;
        int j = i | (1 << BIT);
        u64 a0 = r[i], a1 = r[j];
        u64 a0s = sw2(a0), a1s = sw2(a1);
        r[i] = fma2(c00rr, a0, fma2(c00ii, a0s, fma2(c01rr, a1, mul2(c01ii, a1s))));
        r[j] = fma2(c10rr, a0, fma2(c10ii, a0s, fma2(c11rr, a1, mul2(c11ii, a1s))));
    }
}

__device__ __forceinline__ int perm_fn(int k)
{
    int idx = k;
    idx ^= ((idx >> 0) & 1) << 11;
#pragma unroll
    for (int c = 10; c >= 0; c--) {
        int bc = 11 - c, bt = 10 - c;
        idx ^= ((idx >> bc) & 1) << bt;
    }
    return idx;
}

#define SMSZ 4352

__global__ __launch_bounds__(256, 3) void circuit_kernel(const float* __restrict__ q_params,
                                                         const float* __restrict__ W_out,
                                                         const float* __restrict__ b_out,
                                                         float* __restrict__ out)
{
    __shared__ u64 st[SMSZ];
    __shared__ u64 Ug2[NL * NQ * 8];
    __shared__ float red[8];
    __shared__ float sez[NQ];

    int t = threadIdx.x;

    if (t < NL * NQ) {
        float tx = q_params[t * 3 + 0];
        float ty = q_params[t * 3 + 1];
        float tz = q_params[t * 3 + 2];
        float cx, sx, cy, sy, cz, sz;
        sincosf(0.5f * tx, &sx, &cx);
        sincosf(0.5f * ty, &sy, &cy);
        sincosf(0.5f * tz, &sz, &cz);
        float2 M00 = make_float2(cy * cx, sy * sx);
        float2 M01 = make_float2(-sy * cx, -cy * sx);
        float2 M10 = make_float2(sy * cx, -cy * sx);
        float2 M11 = make_float2(cy * cx, -sy * sx);
        float2 u00 = make_float2(cz * M00.x + sz * M00.y, cz * M00.y - sz * M00.x);
        float2 u01 = make_float2(cz * M01.x + sz * M01.y, cz * M01.y - sz * M01.x);
        float2 u10 = make_float2(cz * M10.x - sz * M10.y, cz * M10.y + sz * M10.x);
        float2 u11 = make_float2(cz * M11.x - sz * M11.y, cz * M11.y + sz * M11.x);
        u64* g = &Ug2[t * 8];
        g[0] = pk2(u00.x, u00.x); g[1] = pk2(-u00.y, u00.y);
        g[2] = pk2(u01.x, u01.x); g[3] = pk2(-u01.y, u01.y);
        g[4] = pk2(u10.x, u10.x); g[5] = pk2(-u10.y, u10.y);
        g[6] = pk2(u11.x, u11.x); g[7] = pk2(-u11.y, u11.y);
    }

    u32 psp[8];
#pragma unroll
    for (int i = 0; i < 8; i++) {
        int k0 = (t << 4) | (2 * i);
        int a0 = perm_fn(k0);     a0 += a0 >> 4;
        int a1 = perm_fn(k0 | 1); a1 += a1 >> 4;
        psp[i] = (u32)a0 | ((u32)a1 << 16);
    }

    for (int e = 0; e < ELEMS; e++) {
        int b = blockIdx.x * ELEMS + e;
        __syncthreads();
        if (t < NQ) sez[t] = 0.f;

        u64 r[16];
        float loc = 0.f;
        const float* arow = g_amp + (size_t)b * DIMQ;
#pragma unroll
        for (int ii = 0; ii < 4; ii++) {
            float4 v = ((const float4*)arow)[t * 4 + ii];
            r[ii * 4 + 0] = pk2(v.x, 0.f);
            r[ii * 4 + 1] = pk2(v.y, 0.f);
            r[ii * 4 + 2] = pk2(v.z, 0.f);
            r[ii * 4 + 3] = pk2(v.w, 0.f);
            loc += v.x * v.x + v.y * v.y + v.z * v.z + v.w * v.w;
        }
#pragma unroll
        for (int o = 16; o > 0; o >>= 1) loc += __shfl_xor_sync(0xffffffffu, loc, o);
        if ((t & 31) == 0) red[t >> 5] = loc;
        __syncthreads();
        float tot = 0.f;
#pragma unroll
        for (int i = 0; i < 8; i++) tot += red[i];
        float nrm = sqrtf(tot);
        if (nrm > 1e-8f) {
            float s = 1.f / nrm;
            u64 ss = pk2(s, s);
#pragma unroll
            for (int i = 0; i < 16; i++) r[i] = mul2(r[i], ss);
        } else {
#pragma unroll
            for (int i = 0; i < 16; i++)
                r[i] = (t == 0 && i == 0) ? pk2(1.f, 0.f) : 0ull;
        }

        for (int l = 0; l < NL; l++) {
            int base = l * NQ;
            apply_local<0>(r, &Ug2[(base + 11) * 8]);
            apply_local<1>(r, &Ug2[(base + 10) * 8]);
            apply_local<2>(r, &Ug2[(base + 9) * 8]);
            apply_local<3>(r, &Ug2[(base + 8) * 8]);
            __syncthreads();
#pragma unroll
            for (int i = 0; i < 16; i++) {
                int k = (t << 4) | i;
                st[k + (k >> 4)] = r[i];
            }
            __syncwarp();
#pragma unroll
            for (int i = 0; i < 16; i++) {
                int k = ((t >> 4) << 8) | (i << 4) | (t & 15);
                r[i] = st[k + (k >> 4)];
            }
            apply_local<0>(r, &Ug2[(base + 7) * 8]);
            apply_local<1>(r, &Ug2[(base + 6) * 8]);
            apply_local<2>(r, &Ug2[(base + 5) * 8]);
            apply_local<3>(r, &Ug2[(base + 4) * 8]);
#pragma unroll
            for (int i = 0; i < 16; i++) {
                int k = ((t >> 4) << 8) | (i << 4) | (t & 15);
                st[k + (k >> 4)] = r[i];
            }
            __syncthreads();
#pragma unroll
            for (int i = 0; i < 16; i++) {
                int k = (i << 8) | t;
                r[i] = st[k + (k >> 4)];
            }
            apply_local<0>(r, &Ug2[(base + 3) * 8]);
            apply_local<1>(r, &Ug2[(base + 2) * 8]);
            apply_local<2>(r, &Ug2[(base + 1) * 8]);
            apply_local<3>(r, &Ug2[(base + 0) * 8]);
#pragma unroll
            for (int i = 0; i < 16; i++) {
                int k = (i << 8) | t;
                st[k + (k >> 4)] = r[i];
            }
            __syncthreads();
#pragma unroll
            for (int i = 0; i < 16; i++) {
                int a = (psp[i >> 1] >> ((i & 1) * 16)) & 0xFFFF;
                r[i] = st[a];
            }
        }

        float p[16];
        float ptot = 0.f;
#pragma unroll
        for (int i = 0; i < 16; i++) {
            float x, y;
            upk2(r[i], x, y);
            p[i] = x * x + y * y;
            ptot += p[i];
        }
        float sb[4];
#pragma unroll
        for (int bp = 0; bp < 4; bp++) {
            float s = 0.f;
#pragma unroll
            for (int i = 0; i < 16; i++) s += ((i >> bp) & 1) ? -p[i] : p[i];
            sb[bp] = s;
        }
#pragma unroll
        for (int q = 0; q < NQ; q++) {
            int bp = 11 - q;
            float v = (bp < 4) ? sb[bp] : (((t >> (bp - 4)) & 1) ? -ptot : ptot);
#pragma unroll
            for (int o = 16; o > 0; o >>= 1) v += __shfl_xor_sync(0xffffffffu, v, o);
            if ((t & 31) == 0) atomicAdd(&sez[q], v);
        }
        __syncthreads();

        if (t < ODIM) {
            float acc = b_out[t];
#pragma unroll
            for (int i = 0; i < NQ; i++) acc += W_out[t * NQ + i] * sez[i];
            out[(size_t)b * ODIM + t] = acc;
        }
    }
}

// ---------------------------------------------------------------------------
extern "C" void kernel_launch(void* const* d_in, const int* in_sizes, int n_in,
                              void* d_out, int out_size)
{
    const float* x        = (const float*)d_in[0];
    const float* W_in     = (const float*)d_in[1];
    const float* b_in     = (const float*)d_in[2];
    const float* q_params = (const float*)d_in[3];
    const float* W_out    = (const float*)d_in[4];
    const float* b_out    = (const float*)d_in[5];
    float* out = (float*)d_out;

    cudaFuncSetAttribute(mma_kernel, cudaFuncAttributeMaxDynamicSharedMemorySize,
                         2 * STAGE_BYTES + 1024);

    split_kernel<<<XSPLIT_BLOCKS + WSPLIT_BLOCKS, 256>>>(x, W_in);

    dim3 gmm(DIMQ / BN, BATCHQ / BM);   // 64 x 64 = 4096 CTAs
    mma_kernel<<<gmm, 256, 2 * STAGE_BYTES + 1024>>>(b_in);

    circuit_kernel<<<CIRC_GRID, 256>>>(q_params, W_out, b_out, out);
}

// round 17
// speedup vs baseline: 1.1385x; 1.1353x over previous
#include <cuda_runtime.h>
#include <cuda_bf16.h>
#include <math.h>

#define DIMQ 4096
#define NQ 12
#define NL 6
#define BATCHQ 8192
#define KDIM 1024
#define ODIM 16

// GEMM: 128x64 tile, 2-stage, 2 CTAs/SM (R15 form)
#define BM 128
#define BN 64
#define BK 64
#define A_TILE 16384
#define B_TILE 8192
#define STAGE_BYTES (2 * A_TILE + 2 * B_TILE)   // 48 KB
#define N_ITERS (KDIM / BK)

#define ELEMS 4
#define CIRC_GRID (BATCHQ / ELEMS)

#define XSPLIT_BLOCKS ((BATCHQ * KDIM / 4) / 256)
#define WSPLIT_BLOCKS ((DIMQ * KDIM / 4) / 256)

typedef unsigned long long u64;
typedef unsigned int u32;

__device__ float g_amp[(size_t)BATCHQ * DIMQ];
__device__ __nv_bfloat16 g_xhi[(size_t)BATCHQ * KDIM];
__device__ __nv_bfloat16 g_xlo[(size_t)BATCHQ * KDIM];
__device__ __nv_bfloat16 g_whi[(size_t)DIMQ * KDIM];
__device__ __nv_bfloat16 g_wlo[(size_t)DIMQ * KDIM];

// gate coefficients: computed on device, staged through a device buffer into
// __constant__ so the circuit's FFMA2 reads them via the const/uniform port
__device__ u64 g_gates[NL * NQ * 8];
__constant__ u64 c_Ug2[NL * NQ * 8];

__device__ __forceinline__ float clip10(float v) { return fminf(fmaxf(v, -10.f), 10.f); }

// ---- packed f32x2 helpers ----
__device__ __forceinline__ u64 pk2(float x, float y) {
    u64 r;
    asm("mov.b64 %0, {%1, %2};" : "=l"(r) : "r"(__float_as_uint(x)), "r"(__float_as_uint(y)));
    return r;
}
__device__ __forceinline__ void upk2(u64 v, float& x, float& y) {
    unsigned lo, hi;
    asm("mov.b64 {%0, %1}, %2;" : "=r"(lo), "=r"(hi) : "l"(v));
    x = __uint_as_float(lo); y = __uint_as_float(hi);
}
__device__ __forceinline__ u64 fma2(u64 a, u64 b, u64 c) {
    u64 d;
    asm("fma.rn.f32x2 %0, %1, %2, %3;" : "=l"(d) : "l"(a), "l"(b), "l"(c));
    return d;
}
__device__ __forceinline__ u64 mul2(u64 a, u64 b) {
    u64 d;
    asm("mul.rn.f32x2 %0, %1, %2;" : "=l"(d) : "l"(a), "l"(b));
    return d;
}
__device__ __forceinline__ u64 sw2(u64 v) {
    unsigned lo, hi;
    asm("mov.b64 {%0, %1}, %2;" : "=r"(lo), "=r"(hi) : "l"(v));
    u64 r;
    asm("mov.b64 %0, {%1, %2};" : "=l"(r) : "r"(hi), "r"(lo));
    return r;
}

// ---- smem / async helpers ----
__device__ __forceinline__ u32 smem_u32(const void* p) {
    u32 a;
    asm("{ .reg .u64 t; cvta.to.shared.u64 t, %1; cvt.u32.u64 %0, t; }" : "=r"(a) : "l"(p));
    return a;
}
__device__ __forceinline__ u32 sw128(u32 off) { return off ^ ((off >> 3) & 0x70); }
__device__ __forceinline__ void cp16(u32 dst, const void* src) {
    asm volatile("cp.async.cg.shared.global [%0], [%1], 16;" :: "r"(dst), "l"(src) : "memory");
}
template <int N> __device__ __forceinline__ void cp_wait() {
    asm volatile("cp.async.wait_group %0;" :: "n"(N) : "memory");
}
__device__ __forceinline__ void ldm_x4(u32 addr, u32& r0, u32& r1, u32& r2, u32& r3) {
    asm volatile("ldmatrix.sync.aligned.m8n8.x4.shared.b16 {%0,%1,%2,%3}, [%4];"
                 : "=r"(r0), "=r"(r1), "=r"(r2), "=r"(r3) : "r"(addr));
}
__device__ __forceinline__ void mma16816(float* c, const u32* a, const u32* b) {
    asm volatile(
        "mma.sync.aligned.m16n8k16.row.col.f32.bf16.bf16.f32 "
        "{%0,%1,%2,%3}, {%4,%5,%6,%7}, {%8,%9}, {%0,%1,%2,%3};"
        : "+f"(c[0]), "+f"(c[1]), "+f"(c[2]), "+f"(c[3])
        : "r"(a[0]), "r"(a[1]), "r"(a[2]), "r"(a[3]), "r"(b[0]), "r"(b[1]));
}

// ---------------------------------------------------------------------------
// Gate coefficient kernel (72 threads, once)
// ---------------------------------------------------------------------------
__global__ void gates_kernel(const float* __restrict__ q_params)
{
    int t = threadIdx.x;
    if (t >= NL * NQ) return;
    float tx = q_params[t * 3 + 0];
    float ty = q_params[t * 3 + 1];
    float tz = q_params[t * 3 + 2];
    float cx, sx, cy, sy, cz, sz;
    sincosf(0.5f * tx, &sx, &cx);
    sincosf(0.5f * ty, &sy, &cy);
    sincosf(0.5f * tz, &sz, &cz);
    float2 M00 = make_float2(cy * cx, sy * sx);
    float2 M01 = make_float2(-sy * cx, -cy * sx);
    float2 M10 = make_float2(sy * cx, -cy * sx);
    float2 M11 = make_float2(cy * cx, -sy * sx);
    float2 u00 = make_float2(cz * M00.x + sz * M00.y, cz * M00.y - sz * M00.x);
    float2 u01 = make_float2(cz * M01.x + sz * M01.y, cz * M01.y - sz * M01.x);
    float2 u10 = make_float2(cz * M10.x - sz * M10.y, cz * M10.y + sz * M10.x);
    float2 u11 = make_float2(cz * M11.x - sz * M11.y, cz * M11.y + sz * M11.x);
    u64* g = &g_gates[t * 8];
    g[0] = pk2(u00.x, u00.x); g[1] = pk2(-u00.y, u00.y);
    g[2] = pk2(u01.x, u01.x); g[3] = pk2(-u01.y, u01.y);
    g[4] = pk2(u10.x, u10.x); g[5] = pk2(-u10.y, u10.y);
    g[6] = pk2(u11.x, u11.x); g[7] = pk2(-u11.y, u11.y);
}

// ---------------------------------------------------------------------------
// Merged split kernel
// ---------------------------------------------------------------------------
__global__ __launch_bounds__(256) void split_kernel(const float* __restrict__ x,
                                                    const float* __restrict__ w)
{
    int bid = blockIdx.x;
    bool isX = (bid < XSPLIT_BLOCKS);
    const float* src = isX ? x : w;
    size_t base = isX ? (size_t)bid : (size_t)(bid - XSPLIT_BLOCKS);
    size_t i = base * 256 + threadIdx.x;

    float4 v = ((const float4*)src)[i];
    if (isX) {
        v.x = clip10(v.x); v.y = clip10(v.y); v.z = clip10(v.z); v.w = clip10(v.w);
    }
    __nv_bfloat16 h0 = __float2bfloat16_rn(v.x), h1 = __float2bfloat16_rn(v.y);
    __nv_bfloat16 h2 = __float2bfloat16_rn(v.z), h3 = __float2bfloat16_rn(v.w);
    __nv_bfloat16 l0 = __float2bfloat16_rn(v.x - __bfloat162float(h0));
    __nv_bfloat16 l1 = __float2bfloat16_rn(v.y - __bfloat162float(h1));
    __nv_bfloat16 l2 = __float2bfloat16_rn(v.z - __bfloat162float(h2));
    __nv_bfloat16 l3 = __float2bfloat16_rn(v.w - __bfloat162float(h3));
    uint2 oh, ol;
    oh.x = (u32)__bfloat16_as_ushort(h0) | ((u32)__bfloat16_as_ushort(h1) << 16);
    oh.y = (u32)__bfloat16_as_ushort(h2) | ((u32)__bfloat16_as_ushort(h3) << 16);
    ol.x = (u32)__bfloat16_as_ushort(l0) | ((u32)__bfloat16_as_ushort(l1) << 16);
    ol.y = (u32)__bfloat16_as_ushort(l2) | ((u32)__bfloat16_as_ushort(l3) << 16);
    if (isX) {
        ((uint2*)g_xhi)[i] = oh;
        ((uint2*)g_xlo)[i] = ol;
    } else {
        ((uint2*)g_whi)[i] = oh;
        ((uint2*)g_wlo)[i] = ol;
    }
}

// ---------------------------------------------------------------------------
// HMMA bf16 split GEMM — 128x64 tile, 2-stage double buffer, 2 CTAs/SM
// ---------------------------------------------------------------------------
__device__ __forceinline__ void load_stage(u32 tile0, int buf, int kt,
                                           int rowBase, int colBase, int tid)
{
    u32 SB = tile0 + buf * STAGE_BYTES;
    const __nv_bfloat16* a_h = g_xhi + (size_t)rowBase * KDIM + kt;
    const __nv_bfloat16* a_l = g_xlo + (size_t)rowBase * KDIM + kt;
    const __nv_bfloat16* b_h = g_whi + (size_t)colBase * KDIM + kt;
    const __nv_bfloat16* b_l = g_wlo + (size_t)colBase * KDIM + kt;
#pragma unroll
    for (int i = 0; i < 4; i++) {
        int lin = i * 256 + tid;
        int row = lin >> 3, seg = lin & 7;
        u32 so = sw128((u32)(row * 128 + seg * 16));
        size_t go = (size_t)row * KDIM + seg * 8;
        cp16(SB + so, a_h + go);
        cp16(SB + A_TILE + so, a_l + go);
    }
#pragma unroll
    for (int i = 0; i < 2; i++) {
        int lin = i * 256 + tid;
        int row = lin >> 3, seg = lin & 7;
        u32 so = sw128((u32)(row * 128 + seg * 16));
        size_t go = (size_t)row * KDIM + seg * 8;
        cp16(SB + 2 * A_TILE + so, b_h + go);
        cp16(SB + 2 * A_TILE + B_TILE + so, b_l + go);
    }
    asm volatile("cp.async.commit_group;" ::: "memory");
}

__global__ __launch_bounds__(256, 2) void mma_kernel(const float* __restrict__ bias)
{
    extern __shared__ char dsm[];
    __shared__ float bsh[BN];

    int tid = threadIdx.x;
    int wid = tid >> 5;
    int lane = tid & 31;
    int rowBase = blockIdx.y * BM;
    int colBase = blockIdx.x * BN;
    int wm = (wid >> 2) * 64;
    int wn = (wid & 3) * 16;

    u32 tile0 = (smem_u32(dsm) + 1023u) & ~1023u;

    if (tid < BN) bsh[tid] = bias[colBase + tid];

    u32 aRowOff = (u32)((lane & 15) * 128 + (lane >> 4) * 16);
    u32 bRowOff = (u32)(((lane >> 4) * 8 + (lane & 7)) * 128 + ((lane >> 3) & 1) * 16);

    float acc[4][2][4];
#pragma unroll
    for (int mi = 0; mi < 4; mi++)
#pragma unroll
        for (int ni = 0; ni < 2; ni++)
#pragma unroll
            for (int r = 0; r < 4; r++) acc[mi][ni][r] = 0.f;

    load_stage(tile0, 0, 0, rowBase, colBase, tid);
    load_stage(tile0, 1, BK, rowBase, colBase, tid);

    for (int it = 0; it < N_ITERS; it++) {
        int buf = it & 1;
        if (it == N_ITERS - 1) cp_wait<0>(); else cp_wait<1>();
        __syncthreads();
        u32 SA_h = tile0 + buf * STAGE_BYTES;
        u32 SA_l = SA_h + A_TILE;
        u32 SB_h = SA_h + 2 * A_TILE;
        u32 SB_l = SB_h + B_TILE;

#pragma unroll
        for (int ks = 0; ks < 4; ks++) {
            u32 ah[4][4], al[4][4];
#pragma unroll
            for (int mi = 0; mi < 4; mi++) {
                u32 off = (u32)((wm + mi * 16) * 128 + ks * 32) + aRowOff;
                u32 sa = sw128(off);
                ldm_x4(SA_h + sa, ah[mi][0], ah[mi][1], ah[mi][2], ah[mi][3]);
                ldm_x4(SA_l + sa, al[mi][0], al[mi][1], al[mi][2], al[mi][3]);
            }
            u32 bh[4], bl[4];
            {
                u32 off = (u32)(wn * 128 + ks * 32) + bRowOff;
                u32 sb = sw128(off);
                ldm_x4(SB_h + sb, bh[0], bh[1], bh[2], bh[3]);
                ldm_x4(SB_l + sb, bl[0], bl[1], bl[2], bl[3]);
            }
#pragma unroll
            for (int mi = 0; mi < 4; mi++)
#pragma unroll
                for (int ni = 0; ni < 2; ni++)
                    mma16816(acc[mi][ni], ah[mi], &bh[ni * 2]);
#pragma unroll
            for (int mi = 0; mi < 4; mi++)
#pragma unroll
                for (int ni = 0; ni < 2; ni++)
                    mma16816(acc[mi][ni], ah[mi], &bl[ni * 2]);
#pragma unroll
            for (int mi = 0; mi < 4; mi++)
#pragma unroll
                for (int ni = 0; ni < 2; ni++)
                    mma16816(acc[mi][ni], al[mi], &bh[ni * 2]);
        }
        __syncthreads();
        if (it + 2 < N_ITERS) load_stage(tile0, buf, (it + 2) * BK, rowBase, colBase, tid);
    }

    int r0 = lane >> 2;
    int c0 = (lane & 3) * 2;
#pragma unroll
    for (int mi = 0; mi < 4; mi++) {
        int mrow = rowBase + wm + mi * 16 + r0;
        float* row0 = g_amp + (size_t)mrow * DIMQ;
        float* row1 = row0 + (size_t)8 * DIMQ;
#pragma unroll
        for (int ni = 0; ni < 2; ni++) {
            int col = wn + ni * 8 + c0;
            float2 v0 = make_float2(acc[mi][ni][0] + bsh[col], acc[mi][ni][1] + bsh[col + 1]);
            float2 v1 = make_float2(acc[mi][ni][2] + bsh[col], acc[mi][ni][3] + bsh[col + 1]);
            *(float2*)(row0 + colBase + col) = v0;
            *(float2*)(row1 + colBase + col) = v1;
        }
    }
}

// ---------------------------------------------------------------------------
// Circuit kernel — gate coefficients from __constant__ (const/uniform port:
// FFMA2 reads only 2 RF operands -> rt 3 -> 2 if the encoding exists)
// ---------------------------------------------------------------------------
template <int BIT>
__device__ __forceinline__ void apply_local(u64 r[16], int gidx)
{
    const u64* g = &c_Ug2[gidx * 8];
    u64 c00rr = g[0], c00ii = g[1], c01rr = g[2], c01ii = g[3];
    u64 c10rr = g[4], c10ii = g[5], c11rr = g[6], c11ii = g[7];
#pragma unroll
    for (int i = 0; i < 16; i++) {
        if ((i >> BIT) & 1) continue;
        int j = i | (1 << BIT);
        u64 a0 = r[i], a1 = r[j];
        u64 a0s = sw2(a0), a1s = sw2(a1);
        r[i] = fma2(c00rr, a0, fma2(c00ii, a0s, fma2(c01rr, a1, mul2(c01ii, a1s))));
        r[j] = fma2(c10rr, a0, fma2(c10ii, a0s, fma2(c11rr, a1, mul2(c11ii, a1s))));
    }
}

__device__ __forceinline__ int perm_fn(int k)
{
    int idx = k;
    idx ^= ((idx >> 0) & 1) << 11;
#pragma unroll
    for (int c = 10; c >= 0; c--) {
        int bc = 11 - c, bt = 10 - c;
        idx ^= ((idx >> bc) & 1) << bt;
    }
    return idx;
}

#define SMSZ 4352

__global__ __launch_bounds__(256, 3) void circuit_kernel(const float* __restrict__ W_out,
                                                         const float* __restrict__ b_out,
                                                         float* __restrict__ out)
{
    __shared__ u64 st[SMSZ];
    __shared__ float red[8];
    __shared__ float sez[NQ];

    int t = threadIdx.x;

    u32 psp[8];
#pragma unroll
    for (int i = 0; i < 8; i++) {
        int k0 = (t << 4) | (2 * i);
        int a0 = perm_fn(k0);     a0 += a0 >> 4;
        int a1 = perm_fn(k0 | 1); a1 += a1 >> 4;
        psp[i] = (u32)a0 | ((u32)a1 << 16);
    }

    for (int e = 0; e < ELEMS; e++) {
        int b = blockIdx.x * ELEMS + e;
        __syncthreads();
        if (t < NQ) sez[t] = 0.f;

        u64 r[16];
        float loc = 0.f;
        const float* arow = g_amp + (size_t)b * DIMQ;
#pragma unroll
        for (int ii = 0; ii < 4; ii++) {
            float4 v = ((const float4*)arow)[t * 4 + ii];
            r[ii * 4 + 0] = pk2(v.x, 0.f);
            r[ii * 4 + 1] = pk2(v.y, 0.f);
            r[ii * 4 + 2] = pk2(v.z, 0.f);
            r[ii * 4 + 3] = pk2(v.w, 0.f);
            loc += v.x * v.x + v.y * v.y + v.z * v.z + v.w * v.w;
        }
#pragma unroll
        for (int o = 16; o > 0; o >>= 1) loc += __shfl_xor_sync(0xffffffffu, loc, o);
        if ((t & 31) == 0) red[t >> 5] = loc;
        __syncthreads();
        float tot = 0.f;
#pragma unroll
        for (int i = 0; i < 8; i++) tot += red[i];
        float nrm = sqrtf(tot);
        if (nrm > 1e-8f) {
            float s = 1.f / nrm;
            u64 ss = pk2(s, s);
#pragma unroll
            for (int i = 0; i < 16; i++) r[i] = mul2(r[i], ss);
        } else {
#pragma unroll
            for (int i = 0; i < 16; i++)
                r[i] = (t == 0 && i == 0) ? pk2(1.f, 0.f) : 0ull;
        }

        for (int l = 0; l < NL; l++) {
            int base = l * NQ;
            apply_local<0>(r, base + 11);
            apply_local<1>(r, base + 10);
            apply_local<2>(r, base + 9);
            apply_local<3>(r, base + 8);
            __syncthreads();
#pragma unroll
            for (int i = 0; i < 16; i++) {
                int k = (t << 4) | i;
                st[k + (k >> 4)] = r[i];
            }
            __syncwarp();
#pragma unroll
            for (int i = 0; i < 16; i++) {
                int k = ((t >> 4) << 8) | (i << 4) | (t & 15);
                r[i] = st[k + (k >> 4)];
            }
            apply_local<0>(r, base + 7);
            apply_local<1>(r, base + 6);
            apply_local<2>(r, base + 5);
            apply_local<3>(r, base + 4);
#pragma unroll
            for (int i = 0; i < 16; i++) {
                int k = ((t >> 4) << 8) | (i << 4) | (t & 15);
                st[k + (k >> 4)] = r[i];
            }
            __syncthreads();
#pragma unroll
            for (int i = 0; i < 16; i++) {
                int k = (i << 8) | t;
                r[i] = st[k + (k >> 4)];
            }
            apply_local<0>(r, base + 3);
            apply_local<1>(r, base + 2);
            apply_local<2>(r, base + 1);
            apply_local<3>(r, base + 0);
#pragma unroll
            for (int i = 0; i < 16; i++) {
                int k = (i << 8) | t;
                st[k + (k >> 4)] = r[i];
            }
            __syncthreads();
#pragma unroll
            for (int i = 0; i < 16; i++) {
                int a = (psp[i >> 1] >> ((i & 1) * 16)) & 0xFFFF;
                r[i] = st[a];
            }
        }

        float p[16];
        float ptot = 0.f;
#pragma unroll
        for (int i = 0; i < 16; i++) {
            float x, y;
            upk2(r[i], x, y);
            p[i] = x * x + y * y;
            ptot += p[i];
        }
        float sb[4];
#pragma unroll
        for (int bp = 0; bp < 4; bp++) {
            float s = 0.f;
#pragma unroll
            for (int i = 0; i < 16; i++) s += ((i >> bp) & 1) ? -p[i] : p[i];
            sb[bp] = s;
        }
#pragma unroll
        for (int q = 0; q < NQ; q++) {
            int bp = 11 - q;
            float v = (bp < 4) ? sb[bp] : (((t >> (bp - 4)) & 1) ? -ptot : ptot);
#pragma unroll
            for (int o = 16; o > 0; o >>= 1) v += __shfl_xor_sync(0xffffffffu, v, o);
            if ((t & 31) == 0) atomicAdd(&sez[q], v);
        }
        __syncthreads();

        if (t < ODIM) {
            float acc = b_out[t];
#pragma unroll
            for (int i = 0; i < NQ; i++) acc += W_out[t * NQ + i] * sez[i];
            out[(size_t)b * ODIM + t] = acc;
        }
    }
}

// ---------------------------------------------------------------------------
extern "C" void kernel_launch(void* const* d_in, const int* in_sizes, int n_in,
                              void* d_out, int out_size)
{
    const float* x        = (const float*)d_in[0];
    const float* W_in     = (const float*)d_in[1];
    const float* b_in     = (const float*)d_in[2];
    const float* q_params = (const float*)d_in[3];
    const float* W_out    = (const float*)d_in[4];
    const float* b_out    = (const float*)d_in[5];
    float* out = (float*)d_out;

    cudaFuncSetAttribute(mma_kernel, cudaFuncAttributeMaxDynamicSharedMemorySize,
                         2 * STAGE_BYTES + 1024);

    // gate coefficients -> device buffer -> __constant__
    // (resolve BOTH symbols to device addresses; R16 bug was passing the
    //  host-side shadow of g_gates as the memcpy src)
    gates_kernel<<<1, 128>>>(q_params);
    void* dst = 0;
    void* src = 0;
    cudaGetSymbolAddress(&dst, c_Ug2);
    cudaGetSymbolAddress(&src, g_gates);
    cudaMemcpyAsync(dst, src, NL * NQ * 8 * sizeof(u64),
                    cudaMemcpyDeviceToDevice, 0);

    split_kernel<<<XSPLIT_BLOCKS + WSPLIT_BLOCKS, 256>>>(x, W_in);

    dim3 gmm(DIMQ / BN, BATCHQ / BM);
    mma_kernel<<<gmm, 256, 2 * STAGE_BYTES + 1024>>>(b_in);

    circuit_kernel<<<CIRC_GRID, 256>>>(W_out, b_out, out);
}